// round 1
// baseline (speedup 1.0000x reference)
#include <cuda_runtime.h>
#include <math.h>

#define NN 100000
#define EE 625000
#define DD 128
#define CC 40

// ---------------- scratch (device globals; no allocation allowed) ----------------
__device__ float  g_t   [(size_t)NN * DD];   // pre-scaled GEMM output t' = dinv * (h@W)
__device__ float  g_agg [(size_t)NN * DD];   // aggregation accumulator
__device__ float  g_h   [(size_t)NN * DD];   // current activations
__device__ float  g_r   [(size_t)NN * DD];   // residual
__device__ float  g_dinv[NN];
__device__ int    g_deg [NN];
__device__ double g_stats[2 * DD];           // column sum, sumsq
__device__ float  g_ab  [2 * DD];            // BN fused scale a, shift bb
__device__ int    g_flag64;                  // 1 if edge_index is int64

// ---------------- edge dtype detection ----------------
// If int64 (little-endian, values < 2^31), every odd int32 word is 0.
__global__ void gcn_detect_kernel(const int* __restrict__ ei32) {
    __shared__ int anynz;
    if (threadIdx.x == 0) anynz = 0;
    __syncthreads();
    int v = 0;
    for (int i = threadIdx.x; i < 4096; i += blockDim.x)
        v |= ei32[2 * i + 1];
    if (v) atomicOr(&anynz, 1);
    __syncthreads();
    if (threadIdx.x == 0) g_flag64 = (anynz == 0) ? 1 : 0;
}

__device__ __forceinline__ int ld_edge(const void* ei, long long idx) {
    if (g_flag64) return (int)((const long long*)ei)[idx];
    return ((const int*)ei)[idx];
}

// ---------------- degree / dinv ----------------
__global__ void gcn_degree_kernel(const void* __restrict__ ei) {
    int e = blockIdx.x * blockDim.x + threadIdx.x;
    if (e >= EE) return;
    int dst = ld_edge(ei, (long long)EE + e);
    atomicAdd(&g_deg[dst], 1);
}

__global__ void gcn_dinv_kernel() {
    int i = blockIdx.x * blockDim.x + threadIdx.x;
    if (i < NN) g_dinv[i] = rsqrtf((float)(g_deg[i] + 1));  // +1 self loop; deg>0 always
}

// ---------------- GEMM: t'[i,:] = dinv[i] * (X[i,:] @ W)  ; also agg = t' ----------------
// 64 rows x 128 cols per block, 256 threads, each thread 4x8 outputs.
#define SX_STRIDE 132  // padded row stride (floats); 528B keeps float4 alignment, kills conflicts
extern __shared__ float gcn_smem[];
__global__ void gcn_gemm_kernel(const float* __restrict__ X, const float* __restrict__ W) {
    float* sW = gcn_smem;               // [128][128]
    float* sx = gcn_smem + DD * DD;     // [64][SX_STRIDE]
    const int tid  = threadIdx.x;
    const int row0 = blockIdx.x * 64;

    // load W (16384 floats -> 64 per thread, float4)
    for (int i = tid; i < DD * DD / 4; i += 256)
        ((float4*)sW)[i] = ((const float4*)W)[i];
    // load x tile (64 rows x 128 cols; float4, coalesced)
    for (int i = tid; i < 64 * 32; i += 256) {
        int r  = i >> 5;
        int k4 = i & 31;
        int gr = row0 + r;
        float4 v = (gr < NN) ? ((const float4*)(X + (size_t)gr * DD))[k4]
                             : make_float4(0.f, 0.f, 0.f, 0.f);
        *(float4*)(sx + r * SX_STRIDE + k4 * 4) = v;
    }
    __syncthreads();

    const int tn = tid & 15;   // col group: 8 cols
    const int tm = tid >> 4;   // row group: 4 rows
    const int cb = tn * 8;
    const int rb = tm * 4;

    float acc[4][8];
#pragma unroll
    for (int m = 0; m < 4; m++)
#pragma unroll
        for (int n = 0; n < 8; n++) acc[m][n] = 0.f;

#pragma unroll 8
    for (int k = 0; k < DD; k++) {
        float a0 = sx[(rb + 0) * SX_STRIDE + k];
        float a1 = sx[(rb + 1) * SX_STRIDE + k];
        float a2 = sx[(rb + 2) * SX_STRIDE + k];
        float a3 = sx[(rb + 3) * SX_STRIDE + k];
        float4 b0 = *(float4*)&sW[k * DD + cb];
        float4 b1 = *(float4*)&sW[k * DD + cb + 4];
        float bb[8] = {b0.x, b0.y, b0.z, b0.w, b1.x, b1.y, b1.z, b1.w};
#pragma unroll
        for (int n = 0; n < 8; n++) {
            acc[0][n] += a0 * bb[n];
            acc[1][n] += a1 * bb[n];
            acc[2][n] += a2 * bb[n];
            acc[3][n] += a3 * bb[n];
        }
    }

#pragma unroll
    for (int m = 0; m < 4; m++) {
        int gr = row0 + rb + m;
        if (gr < NN) {
            float s = g_dinv[gr];
#pragma unroll
            for (int n = 0; n < 8; n += 4) {
                float4 v = make_float4(acc[m][n] * s, acc[m][n + 1] * s,
                                       acc[m][n + 2] * s, acc[m][n + 3] * s);
                *(float4*)&g_t  [(size_t)gr * DD + cb + n] = v;
                *(float4*)&g_agg[(size_t)gr * DD + cb + n] = v;  // self-loop term pre-seeded
            }
        }
    }
}

// ---------------- scatter: agg[dst,:] += t'[src,:]  (one warp per edge) ----------------
__global__ void gcn_scatter_kernel(const void* __restrict__ ei) {
    long long widx = (long long)(blockIdx.x * blockDim.x + threadIdx.x) >> 5;
    int lane = threadIdx.x & 31;
    if (widx >= EE) return;
    int src = ld_edge(ei, widx);
    int dst = ld_edge(ei, (long long)EE + widx);
    float4 v = ((const float4*)(g_t + (size_t)src * DD))[lane];
    float* o = g_agg + (size_t)dst * DD + lane * 4;
    atomicAdd(o + 0, v.x);
    atomicAdd(o + 1, v.y);
    atomicAdd(o + 2, v.z);
    atomicAdd(o + 3, v.w);
}

// ---------------- finalize: v = dinv*agg + bias ; accumulate column stats ----------------
__global__ void gcn_finalize_kernel(const float* __restrict__ bias) {
    int d = threadIdx.x;  // 128 threads; thread d owns column d
    float b = bias[d];
    float s1 = 0.f, s2 = 0.f;
    for (int row = blockIdx.x; row < NN; row += gridDim.x) {
        float v = g_dinv[row] * g_agg[(size_t)row * DD + d] + b;
        g_t[(size_t)row * DD + d] = v;  // t' no longer needed; reuse
        s1 += v;
        s2 += v * v;
    }
    atomicAdd(&g_stats[d],      (double)s1);
    atomicAdd(&g_stats[DD + d], (double)s2);
}

// ---------------- BN coefficients ----------------
__global__ void gcn_bncoef_kernel(const float* __restrict__ gamma,
                                  const float* __restrict__ beta) {
    int d = threadIdx.x;
    double mu  = g_stats[d] / (double)NN;
    double var = g_stats[DD + d] / (double)NN - mu * mu;
    float a = gamma[d] * rsqrtf((float)var + 1e-5f);
    g_ab[d]      = a;
    g_ab[DD + d] = beta[d] - (float)mu * a;
}

// ---------------- BN + ReLU + (residual) + row L2 norm (one warp per row) ----------------
// mode 0: no residual add, write r=h ; mode 1: add r, write r=h ; mode 2: add r, no r write
__global__ void gcn_bnapply_kernel(int mode) {
    long long row = (long long)(blockIdx.x * blockDim.x + threadIdx.x) >> 5;
    int lane = threadIdx.x & 31;
    if (row >= NN) return;
    float4 v  = ((const float4*)(g_t + (size_t)row * DD))[lane];
    float4 a  = ((const float4*)&g_ab[0])[lane];
    float4 bb = ((const float4*)&g_ab[DD])[lane];
    float y0 = fmaxf(v.x * a.x + bb.x, 0.f);
    float y1 = fmaxf(v.y * a.y + bb.y, 0.f);
    float y2 = fmaxf(v.z * a.z + bb.z, 0.f);
    float y3 = fmaxf(v.w * a.w + bb.w, 0.f);
    if (mode >= 1) {
        float4 r = ((const float4*)(g_r + (size_t)row * DD))[lane];
        y0 += r.x; y1 += r.y; y2 += r.z; y3 += r.w;
    }
    float ss = y0 * y0 + y1 * y1 + y2 * y2 + y3 * y3;
#pragma unroll
    for (int o = 16; o; o >>= 1) ss += __shfl_xor_sync(0xFFFFFFFFu, ss, o);
    float inv = 1.f / fmaxf(sqrtf(ss), 1e-12f);
    float4 o4 = make_float4(y0 * inv, y1 * inv, y2 * inv, y3 * inv);
    ((float4*)(g_h + (size_t)row * DD))[lane] = o4;
    if (mode <= 1) ((float4*)(g_r + (size_t)row * DD))[lane] = o4;
}

// ---------------- output: logits = h @ Wout + bout  (32 rows per block) ----------------
__global__ void gcn_out_kernel(const float* __restrict__ Wout,
                               const float* __restrict__ bout,
                               float* __restrict__ out) {
    __shared__ float sW[DD * CC];      // 20 KB
    __shared__ float sh[32][SX_STRIDE]; // padded, 16.5 KB
    int tid = threadIdx.x;
    for (int i = tid; i < DD * CC; i += 256) sW[i] = Wout[i];
    int row0 = blockIdx.x * 32;
    for (int i = tid; i < 32 * 32; i += 256) {
        int r  = i >> 5;
        int k4 = i & 31;
        int gr = row0 + r;
        float4 v = (gr < NN) ? ((const float4*)(g_h + (size_t)gr * DD))[k4]
                             : make_float4(0.f, 0.f, 0.f, 0.f);
        *(float4*)&sh[r][k4 * 4] = v;
    }
    __syncthreads();
    for (int i = tid; i < 32 * CC; i += 256) {
        int r = i / CC, c = i % CC;
        float acc = 0.f;
#pragma unroll 8
        for (int k = 0; k < DD; k++) acc += sh[r][k] * sW[k * CC + c];
        int gr = row0 + r;
        if (gr < NN) out[(size_t)gr * CC + c] = acc + bout[c];
    }
}

// ---------------- launch ----------------
extern "C" void kernel_launch(void* const* d_in, const int* in_sizes, int n_in,
                              void* d_out, int out_size) {
    const float* x    = (const float*)d_in[0];
    const void*  ei   = d_in[1];
    const float* W1   = (const float*)d_in[2];
    const float* b1   = (const float*)d_in[3];
    const float* W2   = (const float*)d_in[4];
    const float* b2   = (const float*)d_in[5];
    const float* W3   = (const float*)d_in[6];
    const float* b3   = (const float*)d_in[7];
    const float* g1   = (const float*)d_in[8];
    const float* be1  = (const float*)d_in[9];
    const float* g2   = (const float*)d_in[10];
    const float* be2  = (const float*)d_in[11];
    const float* g3   = (const float*)d_in[12];
    const float* be3  = (const float*)d_in[13];
    const float* Wout = (const float*)d_in[14];
    const float* bout = (const float*)d_in[15];

    void *deg_p = nullptr, *stats_p = nullptr, *h_p = nullptr;
    cudaGetSymbolAddress(&deg_p,   g_deg);
    cudaGetSymbolAddress(&stats_p, g_stats);
    cudaGetSymbolAddress(&h_p,     g_h);

    const int gemm_smem = (DD * DD + 64 * SX_STRIDE) * (int)sizeof(float);  // 99328 B
    cudaFuncSetAttribute(gcn_gemm_kernel,
                         cudaFuncAttributeMaxDynamicSharedMemorySize, gemm_smem);

    // graph structure
    gcn_detect_kernel<<<1, 256>>>((const int*)ei);
    cudaMemsetAsync(deg_p, 0, NN * sizeof(int));
    gcn_degree_kernel<<<(EE + 255) / 256, 256>>>(ei);
    gcn_dinv_kernel<<<(NN + 255) / 256, 256>>>();

    const int gemm_blocks    = (NN + 63) / 64;           // 1563
    const int scatter_blocks = (EE * 32) / 256;          // 78125 (exact)
    const int bn_blocks      = (NN * 32) / 256;          // 12500 (exact)

    const float* layer_W[3]  = {W1, W2, W3};
    const float* layer_b[3]  = {b1, b2, b3};
    const float* layer_g[3]  = {g1, g2, g3};
    const float* layer_be[3] = {be1, be2, be3};

    for (int l = 0; l < 3; l++) {
        const float* in_ptr = (l == 0) ? x : (const float*)h_p;
        cudaMemsetAsync(stats_p, 0, 2 * DD * sizeof(double));
        gcn_gemm_kernel<<<gemm_blocks, 256, gemm_smem>>>(in_ptr, layer_W[l]);
        gcn_scatter_kernel<<<scatter_blocks, 256>>>(ei);
        gcn_finalize_kernel<<<512, 128>>>(layer_b[l]);
        gcn_bncoef_kernel<<<1, 128>>>(layer_g[l], layer_be[l]);
        gcn_bnapply_kernel<<<bn_blocks, 256>>>(l == 0 ? 0 : (l == 1 ? 1 : 2));
    }

    gcn_out_kernel<<<(NN + 31) / 32, 256>>>(Wout, bout, (float*)d_out);
}

// round 2
// speedup vs baseline: 1.6732x; 1.6732x over previous
#include <cuda_runtime.h>
#include <math.h>

#define NN 100000
#define EE 625000
#define DD 128
#define CC 40
#define SCAN_BLOCKS 391   // ceil(NN/256)

// ---------------- scratch (device globals; no allocation allowed) ----------------
__device__ float  g_t   [(size_t)NN * DD];   // pre-scaled GEMM output t' = dinv * (h@W)
__device__ float  g_agg [(size_t)NN * DD];   // aggregated + biased conv output
__device__ float  g_h   [(size_t)NN * DD];   // current activations
__device__ float  g_r   [(size_t)NN * DD];   // residual
__device__ float  g_dinv[NN];
__device__ int    g_deg [NN];
__device__ int    g_rowstart[NN];
__device__ int    g_cursor[NN];              // after fill: row end
__device__ int    g_csr[EE];                 // src indices grouped by dst
__device__ int    g_bsums[512];
__device__ double g_stats[2 * DD];           // column sum, sumsq
__device__ float  g_ab  [2 * DD];            // BN fused scale a, shift bb
__device__ int    g_flag64;                  // 1 if edge_index is int64

// ---------------- edge dtype detection ----------------
__global__ void gcn_detect_kernel(const int* __restrict__ ei32) {
    __shared__ int anynz;
    if (threadIdx.x == 0) anynz = 0;
    __syncthreads();
    int v = 0;
    for (int i = threadIdx.x; i < 4096; i += blockDim.x)
        v |= ei32[2 * i + 1];
    if (v) atomicOr(&anynz, 1);
    __syncthreads();
    if (threadIdx.x == 0) g_flag64 = (anynz == 0) ? 1 : 0;
}

__device__ __forceinline__ int ld_edge(const void* ei, long long idx) {
    if (g_flag64) return (int)((const long long*)ei)[idx];
    return ((const int*)ei)[idx];
}

// ---------------- degree / dinv ----------------
__global__ void gcn_degree_kernel(const void* __restrict__ ei) {
    int e = blockIdx.x * blockDim.x + threadIdx.x;
    if (e >= EE) return;
    int dst = ld_edge(ei, (long long)EE + e);
    atomicAdd(&g_deg[dst], 1);
}

__global__ void gcn_dinv_kernel() {
    int i = blockIdx.x * blockDim.x + threadIdx.x;
    if (i < NN) g_dinv[i] = rsqrtf((float)(g_deg[i] + 1));  // +1 self loop
}

// ---------------- CSR build: 2-level exclusive scan + fill ----------------
__global__ void gcn_scan1_kernel() {   // per-block sums of deg
    __shared__ int sh[256];
    int i = blockIdx.x * 256 + threadIdx.x;
    sh[threadIdx.x] = (i < NN) ? g_deg[i] : 0;
    __syncthreads();
    for (int o = 128; o; o >>= 1) {
        if (threadIdx.x < o) sh[threadIdx.x] += sh[threadIdx.x + o];
        __syncthreads();
    }
    if (threadIdx.x == 0) g_bsums[blockIdx.x] = sh[0];
}

__global__ void gcn_scan2_kernel() {   // exclusive scan of 391 block sums (1 block, 512 thr)
    __shared__ int sh[512];
    int tid = threadIdx.x;
    int orig = (tid < SCAN_BLOCKS) ? g_bsums[tid] : 0;
    sh[tid] = orig;
    for (int o = 1; o < 512; o <<= 1) {
        __syncthreads();
        int v = (tid >= o) ? sh[tid - o] : 0;
        __syncthreads();
        sh[tid] += v;
    }
    __syncthreads();
    if (tid < SCAN_BLOCKS) g_bsums[tid] = sh[tid] - orig;
}

__global__ void gcn_scan3_kernel() {   // per-element exclusive scan -> rowstart, cursor
    __shared__ int wsum[8];
    int tid = threadIdx.x;
    int lane = tid & 31, wid = tid >> 5;
    int i = blockIdx.x * 256 + tid;
    int v = (i < NN) ? g_deg[i] : 0;
    int incl = v;
#pragma unroll
    for (int d = 1; d < 32; d <<= 1) {
        int n = __shfl_up_sync(0xFFFFFFFFu, incl, d);
        if (lane >= d) incl += n;
    }
    if (lane == 31) wsum[wid] = incl;
    __syncthreads();
    if (tid < 8) {
        int w = wsum[tid];
        int s = w;
#pragma unroll
        for (int d = 1; d < 8; d <<= 1) {
            int n = __shfl_up_sync(0xFFu, s, d);
            if (tid >= d) s += n;
        }
        wsum[tid] = s - w;   // exclusive
    }
    __syncthreads();
    if (i < NN) {
        int excl = g_bsums[blockIdx.x] + wsum[wid] + incl - v;
        g_rowstart[i] = excl;
        g_cursor[i]   = excl;
    }
}

__global__ void gcn_fill_kernel(const void* __restrict__ ei) {
    int e = blockIdx.x * blockDim.x + threadIdx.x;
    if (e >= EE) return;
    int src = ld_edge(ei, e);
    int dst = ld_edge(ei, (long long)EE + e);
    int pos = atomicAdd(&g_cursor[dst], 1);
    g_csr[pos] = src;
}

// ---------------- GEMM: t'[i,:] = dinv[i] * (X[i,:] @ W) ----------------
#define SX_STRIDE 132
extern __shared__ float gcn_smem[];
__global__ void gcn_gemm_kernel(const float* __restrict__ X, const float* __restrict__ W) {
    float* sW = gcn_smem;               // [128][128]
    float* sx = gcn_smem + DD * DD;     // [64][SX_STRIDE]
    const int tid  = threadIdx.x;
    const int row0 = blockIdx.x * 64;

    for (int i = tid; i < DD * DD / 4; i += 256)
        ((float4*)sW)[i] = ((const float4*)W)[i];
    for (int i = tid; i < 64 * 32; i += 256) {
        int r  = i >> 5;
        int k4 = i & 31;
        int gr = row0 + r;
        float4 v = (gr < NN) ? ((const float4*)(X + (size_t)gr * DD))[k4]
                             : make_float4(0.f, 0.f, 0.f, 0.f);
        *(float4*)(sx + r * SX_STRIDE + k4 * 4) = v;
    }
    __syncthreads();

    const int tn = tid & 15;
    const int tm = tid >> 4;
    const int cb = tn * 8;
    const int rb = tm * 4;

    float acc[4][8];
#pragma unroll
    for (int m = 0; m < 4; m++)
#pragma unroll
        for (int n = 0; n < 8; n++) acc[m][n] = 0.f;

#pragma unroll 8
    for (int k = 0; k < DD; k++) {
        float a0 = sx[(rb + 0) * SX_STRIDE + k];
        float a1 = sx[(rb + 1) * SX_STRIDE + k];
        float a2 = sx[(rb + 2) * SX_STRIDE + k];
        float a3 = sx[(rb + 3) * SX_STRIDE + k];
        float4 b0 = *(float4*)&sW[k * DD + cb];
        float4 b1 = *(float4*)&sW[k * DD + cb + 4];
        float bb[8] = {b0.x, b0.y, b0.z, b0.w, b1.x, b1.y, b1.z, b1.w};
#pragma unroll
        for (int n = 0; n < 8; n++) {
            acc[0][n] += a0 * bb[n];
            acc[1][n] += a1 * bb[n];
            acc[2][n] += a2 * bb[n];
            acc[3][n] += a3 * bb[n];
        }
    }

#pragma unroll
    for (int m = 0; m < 4; m++) {
        int gr = row0 + rb + m;
        if (gr < NN) {
            float s = g_dinv[gr];
#pragma unroll
            for (int n = 0; n < 8; n += 4) {
                float4 v = make_float4(acc[m][n] * s, acc[m][n + 1] * s,
                                       acc[m][n + 2] * s, acc[m][n + 3] * s);
                *(float4*)&g_t[(size_t)gr * DD + cb + n] = v;
            }
        }
    }
}

// ---------------- gather + finalize + stats: warp per node ----------------
__global__ void gcn_gather_kernel(const float* __restrict__ bias) {
    const int lane = threadIdx.x & 31;
    const int gw   = (blockIdx.x * blockDim.x + threadIdx.x) >> 5;
    const int nw   = (gridDim.x * blockDim.x) >> 5;
    const float4* t4 = (const float4*)g_t;
    float4 bias4 = ((const float4*)bias)[lane];

    float s1x = 0.f, s1y = 0.f, s1z = 0.f, s1w = 0.f;
    float s2x = 0.f, s2y = 0.f, s2z = 0.f, s2w = 0.f;

    for (int node = gw; node < NN; node += nw) {
        int beg = g_rowstart[node];
        int end = g_cursor[node];     // rowstart + deg after fill
        float4 a0 = t4[(size_t)node * 32 + lane];   // self loop
        float4 a1 = make_float4(0.f, 0.f, 0.f, 0.f);
        float4 a2 = make_float4(0.f, 0.f, 0.f, 0.f);
        float4 a3 = make_float4(0.f, 0.f, 0.f, 0.f);
        int i = beg;
        for (; i + 4 <= end; i += 4) {
            int sx0 = g_csr[i], sx1 = g_csr[i + 1], sx2 = g_csr[i + 2], sx3 = g_csr[i + 3];
            float4 v0 = t4[(size_t)sx0 * 32 + lane];
            float4 v1 = t4[(size_t)sx1 * 32 + lane];
            float4 v2 = t4[(size_t)sx2 * 32 + lane];
            float4 v3 = t4[(size_t)sx3 * 32 + lane];
            a0.x += v0.x; a0.y += v0.y; a0.z += v0.z; a0.w += v0.w;
            a1.x += v1.x; a1.y += v1.y; a1.z += v1.z; a1.w += v1.w;
            a2.x += v2.x; a2.y += v2.y; a2.z += v2.z; a2.w += v2.w;
            a3.x += v3.x; a3.y += v3.y; a3.z += v3.z; a3.w += v3.w;
        }
        for (; i < end; i++) {
            int s = g_csr[i];
            float4 v = t4[(size_t)s * 32 + lane];
            a0.x += v.x; a0.y += v.y; a0.z += v.z; a0.w += v.w;
        }
        float di = g_dinv[node];
        float4 v;
        v.x = di * (a0.x + a1.x + a2.x + a3.x) + bias4.x;
        v.y = di * (a0.y + a1.y + a2.y + a3.y) + bias4.y;
        v.z = di * (a0.z + a1.z + a2.z + a3.z) + bias4.z;
        v.w = di * (a0.w + a1.w + a2.w + a3.w) + bias4.w;
        ((float4*)g_agg)[(size_t)node * 32 + lane] = v;
        s1x += v.x; s1y += v.y; s1z += v.z; s1w += v.w;
        s2x += v.x * v.x; s2y += v.y * v.y; s2z += v.z * v.z; s2w += v.w * v.w;
    }

    __shared__ float sh1[DD], sh2[DD];
    for (int i = threadIdx.x; i < DD; i += blockDim.x) { sh1[i] = 0.f; sh2[i] = 0.f; }
    __syncthreads();
    int c = lane * 4;
    atomicAdd(&sh1[c + 0], s1x); atomicAdd(&sh1[c + 1], s1y);
    atomicAdd(&sh1[c + 2], s1z); atomicAdd(&sh1[c + 3], s1w);
    atomicAdd(&sh2[c + 0], s2x); atomicAdd(&sh2[c + 1], s2y);
    atomicAdd(&sh2[c + 2], s2z); atomicAdd(&sh2[c + 3], s2w);
    __syncthreads();
    if (threadIdx.x < DD) {
        atomicAdd(&g_stats[threadIdx.x],      (double)sh1[threadIdx.x]);
        atomicAdd(&g_stats[DD + threadIdx.x], (double)sh2[threadIdx.x]);
    }
}

// ---------------- BN coefficients ----------------
__global__ void gcn_bncoef_kernel(const float* __restrict__ gamma,
                                  const float* __restrict__ beta) {
    int d = threadIdx.x;
    double mu  = g_stats[d] / (double)NN;
    double var = g_stats[DD + d] / (double)NN - mu * mu;
    float a = gamma[d] * rsqrtf((float)var + 1e-5f);
    g_ab[d]      = a;
    g_ab[DD + d] = beta[d] - (float)mu * a;
}

// ---------------- BN + ReLU + (residual) + row L2 norm (warp per row) ----------------
__global__ void gcn_bnapply_kernel(int mode) {
    long long row = (long long)(blockIdx.x * blockDim.x + threadIdx.x) >> 5;
    int lane = threadIdx.x & 31;
    if (row >= NN) return;
    float4 v  = ((const float4*)(g_agg + (size_t)row * DD))[lane];
    float4 a  = ((const float4*)&g_ab[0])[lane];
    float4 bb = ((const float4*)&g_ab[DD])[lane];
    float y0 = fmaxf(v.x * a.x + bb.x, 0.f);
    float y1 = fmaxf(v.y * a.y + bb.y, 0.f);
    float y2 = fmaxf(v.z * a.z + bb.z, 0.f);
    float y3 = fmaxf(v.w * a.w + bb.w, 0.f);
    if (mode >= 1) {
        float4 r = ((const float4*)(g_r + (size_t)row * DD))[lane];
        y0 += r.x; y1 += r.y; y2 += r.z; y3 += r.w;
    }
    float ss = y0 * y0 + y1 * y1 + y2 * y2 + y3 * y3;
#pragma unroll
    for (int o = 16; o; o >>= 1) ss += __shfl_xor_sync(0xFFFFFFFFu, ss, o);
    float inv = 1.f / fmaxf(sqrtf(ss), 1e-12f);
    float4 o4 = make_float4(y0 * inv, y1 * inv, y2 * inv, y3 * inv);
    ((float4*)(g_h + (size_t)row * DD))[lane] = o4;
    if (mode <= 1) ((float4*)(g_r + (size_t)row * DD))[lane] = o4;
}

// ---------------- output: logits = h @ Wout + bout ----------------
__global__ void gcn_out_kernel(const float* __restrict__ Wout,
                               const float* __restrict__ bout,
                               float* __restrict__ out) {
    __shared__ float sW[DD * CC];
    __shared__ float sh[32][SX_STRIDE];
    int tid = threadIdx.x;
    for (int i = tid; i < DD * CC; i += 256) sW[i] = Wout[i];
    int row0 = blockIdx.x * 32;
    for (int i = tid; i < 32 * 32; i += 256) {
        int r  = i >> 5;
        int k4 = i & 31;
        int gr = row0 + r;
        float4 v = (gr < NN) ? ((const float4*)(g_h + (size_t)gr * DD))[k4]
                             : make_float4(0.f, 0.f, 0.f, 0.f);
        *(float4*)&sh[r][k4 * 4] = v;
    }
    __syncthreads();
    for (int i = tid; i < 32 * CC; i += 256) {
        int r = i / CC, c = i % CC;
        float acc = 0.f;
#pragma unroll 8
        for (int k = 0; k < DD; k++) acc += sh[r][k] * sW[k * CC + c];
        int gr = row0 + r;
        if (gr < NN) out[(size_t)gr * CC + c] = acc + bout[c];
    }
}

// ---------------- launch ----------------
extern "C" void kernel_launch(void* const* d_in, const int* in_sizes, int n_in,
                              void* d_out, int out_size) {
    const float* x    = (const float*)d_in[0];
    const void*  ei   = d_in[1];
    const float* W1   = (const float*)d_in[2];
    const float* b1   = (const float*)d_in[3];
    const float* W2   = (const float*)d_in[4];
    const float* b2   = (const float*)d_in[5];
    const float* W3   = (const float*)d_in[6];
    const float* b3   = (const float*)d_in[7];
    const float* g1   = (const float*)d_in[8];
    const float* be1  = (const float*)d_in[9];
    const float* g2   = (const float*)d_in[10];
    const float* be2  = (const float*)d_in[11];
    const float* g3   = (const float*)d_in[12];
    const float* be3  = (const float*)d_in[13];
    const float* Wout = (const float*)d_in[14];
    const float* bout = (const float*)d_in[15];

    void *deg_p = nullptr, *stats_p = nullptr, *h_p = nullptr;
    cudaGetSymbolAddress(&deg_p,   g_deg);
    cudaGetSymbolAddress(&stats_p, g_stats);
    cudaGetSymbolAddress(&h_p,     g_h);

    const int gemm_smem = (DD * DD + 64 * SX_STRIDE) * (int)sizeof(float);
    cudaFuncSetAttribute(gcn_gemm_kernel,
                         cudaFuncAttributeMaxDynamicSharedMemorySize, gemm_smem);

    // graph structure + CSR (once per launch, reused by all 3 layers)
    gcn_detect_kernel<<<1, 256>>>((const int*)ei);
    cudaMemsetAsync(deg_p, 0, NN * sizeof(int));
    gcn_degree_kernel<<<(EE + 255) / 256, 256>>>(ei);
    gcn_dinv_kernel<<<(NN + 255) / 256, 256>>>();
    gcn_scan1_kernel<<<SCAN_BLOCKS, 256>>>();
    gcn_scan2_kernel<<<1, 512>>>();
    gcn_scan3_kernel<<<SCAN_BLOCKS, 256>>>();
    gcn_fill_kernel<<<(EE + 255) / 256, 256>>>(ei);

    const int gemm_blocks   = (NN + 63) / 64;
    const int gather_blocks = 1184;                 // 148 SMs * 8
    const int bn_blocks     = (NN * 32) / 256;

    const float* layer_W[3]  = {W1, W2, W3};
    const float* layer_b[3]  = {b1, b2, b3};
    const float* layer_g[3]  = {g1, g2, g3};
    const float* layer_be[3] = {be1, be2, be3};

    for (int l = 0; l < 3; l++) {
        const float* in_ptr = (l == 0) ? x : (const float*)h_p;
        cudaMemsetAsync(stats_p, 0, 2 * DD * sizeof(double));
        gcn_gemm_kernel<<<gemm_blocks, 256, gemm_smem>>>(in_ptr, layer_W[l]);
        gcn_gather_kernel<<<gather_blocks, 256>>>(layer_b[l]);
        gcn_bncoef_kernel<<<1, 128>>>(layer_g[l], layer_be[l]);
        gcn_bnapply_kernel<<<bn_blocks, 256>>>(l == 0 ? 0 : (l == 1 ? 1 : 2));
    }

    gcn_out_kernel<<<(NN + 31) / 32, 256>>>(Wout, bout, (float*)d_out);
}